// round 16
// baseline (speedup 1.0000x reference)
#include <cuda_runtime.h>
#include <cuda_fp16.h>
#include <cuda_fp8.h>
#include <cstdint>

// Problem constants (fixed by the reference: m = n = 8192, 50 Sinkhorn iters, beta=0.3)
#define MDIM  8192
#define NBLK  152          // GB300 SM count -> one resident wave at occ 1 (152 = 8*19)
#define TPB   1024         // 32 warps/SM -> occ 50% (was 25% at 512; latency wall)
#define TPBC  256          // helper kernels
#define NITER 50
#define BETA  0.3f

// z is carried SCALED: z' = z * 2^20 (true z ~5e-9 underflows fp16).
// The scale cancels in the w update: z' = 64/S, w = 64/colsum' (2^-14 * 2^20 = 2^6).
#define ZSCALE_K 64.0f
#define RQ_FIX   0.015625f // rowq = z*16384 = z' * 16384/2^20 = z'/64

// ---- scratch (device globals: no allocation allowed in kernel_launch) ----
static __device__ uint32_t g_E8[(size_t)MDIM * MDIM / 4]; // E = exp(s) in e4m3 (64 MB)
static __device__ float  g_w[MDIM];                     // w_j = exp(v_j)
static __device__ float  g_z[MDIM];                     // z'_i = exp(u_i)*2^20 (last iter's)
static __device__ float  g_part[(size_t)NBLK * MDIM];   // per-block column partial sums
static __device__ float  g_losspart[NBLK];              // per-block loss partials
static __device__ unsigned g_cnt;                       // grid-barrier arrive counter
static __device__ unsigned g_gen;                       // grid-barrier generation

__device__ __forceinline__ float warp_sum(float v) {
#pragma unroll
    for (int o = 16; o; o >>= 1) v += __shfl_xor_sync(0xffffffffu, v, o);
    return v;
}
__device__ __forceinline__ float warp_max(float v) {
#pragma unroll
    for (int o = 16; o; o >>= 1) v = fmaxf(v, __shfl_xor_sync(0xffffffffu, v, o));
    return v;
}

// ---- packed f32x2 helpers (sm_103a FADD2 via PTX) ----
__device__ __forceinline__ unsigned long long pk2(float x, float y) {
    unsigned long long u; asm("mov.b64 %0,{%1,%2};" : "=l"(u) : "f"(x), "f"(y)); return u;
}
__device__ __forceinline__ void upk2(unsigned long long u, float& x, float& y) {
    asm("mov.b64 {%0,%1},%2;" : "=f"(x), "=f"(y) : "l"(u));
}
__device__ __forceinline__ unsigned long long add2p(unsigned long long a, unsigned long long b) {
    unsigned long long d;
    asm("add.rn.f32x2 %0,%1,%2;" : "=l"(d) : "l"(a), "l"(b));
    return d;
}
// xor-butterfly sum of a packed f32x2 across the warp. Commutative pairwise adds
// -> every lane ends with the bitwise-IDENTICAL total (deterministic).
__device__ __forceinline__ unsigned long long bfly_sum2(unsigned long long v) {
#pragma unroll
    for (int o = 16; o; o >>= 1) {
        float x, y; upk2(v, x, y);
        float x2 = __shfl_xor_sync(0xffffffffu, x, o);
        float y2 = __shfl_xor_sync(0xffffffffu, y, o);
        v = add2p(v, pk2(x2, y2));
    }
    return v;
}

// ---- e4m3x2 -> half2 (measured end-to-end rel_err 1.63e-4; e5m2 was 6.98e-4) ----
__device__ __forceinline__ __half2 cvt8(uint32_t p) {
    __half2_raw r = __nv_cvt_fp8x2_to_halfraw2((__nv_fp8x2_storage_t)(unsigned short)p, __NV_E4M3);
    return *reinterpret_cast<__half2*>(&r);
}

// row lsum from a uint2 (8 e4m3): 4 cvt + 4 hfma2
__device__ __forceinline__ __half2 row_lsum(uint2 u, const __half2* __restrict__ w2) {
    __half2 s = __float2half2_rn(0.f);
    s = __hfma2(cvt8(u.x),        w2[0], s);
    s = __hfma2(cvt8(u.x >> 16),  w2[1], s);
    s = __hfma2(cvt8(u.y),        w2[2], s);
    s = __hfma2(cvt8(u.y >> 16),  w2[3], s);
    return s;
}
// second unpack: accumulate e*z into cacc (raw bytes kept in regs across the sync)
__device__ __forceinline__ void row_cacc(uint2 u, __half2 zh, __half2* __restrict__ cacc) {
    cacc[0] = __hfma2(cvt8(u.x),       zh, cacc[0]);
    cacc[1] = __hfma2(cvt8(u.x >> 16), zh, cacc[1]);
    cacc[2] = __hfma2(cvt8(u.y),       zh, cacc[2]);
    cacc[3] = __hfma2(cvt8(u.y >> 16), zh, cacc[3]);
}

// Device-wide barrier: all NBLK CTAs resident (one wave, occ 1). Deterministic.
__device__ __forceinline__ void grid_bar(unsigned want) {
    __syncthreads();
    if (threadIdx.x == 0) {
        __threadfence();
        unsigned a = atomicAdd(&g_cnt, 1u);
        if (a == NBLK - 1u) {
            atomicExch(&g_cnt, 0u);
            __threadfence();
            atomicExch(&g_gen, want);           // release
        } else {
            while (*((volatile unsigned*)&g_gen) < want) __nanosleep(64);
        }
        __threadfence();                         // acquire
    }
    __syncthreads();
}

// barrier reset + w <- 1  (runs once per graph replay)
__global__ void k_init() {
    int j = blockIdx.x * blockDim.x + threadIdx.x;
    if (j < MDIM) g_w[j] = 1.0f;
    if (j == 0) { g_cnt = 0u; g_gen = 0u; }
}

// E = exp(s) in e4m3 (one pass; iterations read 1/4 of the fp32 bytes, do NO exp)
__global__ void k_convert(const float* __restrict__ in) {
    const float L2E = 1.4426950408889634f;
    size_t i = (size_t)blockIdx.x * blockDim.x + threadIdx.x;   // float4 index
    float4 f = reinterpret_cast<const float4*>(in)[i];
    float e0 = exp2f(f.x * L2E), e1 = exp2f(f.y * L2E);
    float e2 = exp2f(f.z * L2E), e3 = exp2f(f.w * L2E);
    uint32_t lo = __nv_cvt_float2_to_fp8x2(make_float2(e0, e1), __NV_SATFINITE, __NV_E4M3);
    uint32_t hi = __nv_cvt_float2_to_fp8x2(make_float2(e2, e3), __NV_SATFINITE, __NV_E4M3);
    g_E8[i] = lo | (hi << 16);
}

// Persistent multiplicative Sinkhorn, e4m3 storage + fp16 inner math, 1024 threads.
//   S_i = sum_j E_ij*w_j ; z'_i = 64/S_i ; colsum'_j = sum_i E_ij*z'_i ; w_j = 64/colsum'_j
// Thread t owns cols [8t, 8t+8) (uint2/row). Groups of 4 rows, ONE __syncthreads
// per group; next group's loads issued into nxt[] BEFORE the sync (overlap);
// raw bytes re-unpacked after the sync for cacc (keeps regs under the 64 cap).
// Cross-warp reduce = packed xor-butterfly (no serial tree, all lanes identical).
__global__ void __launch_bounds__(TPB, 1) k_sinkhorn() {
    const int tid = threadIdx.x;
    const int b   = blockIdx.x;
    const int r0  = (b * MDIM) / NBLK;
    const int r1  = ((b + 1) * MDIM) / NBLK;
    const int nrows = r1 - r0;

    // column-reduce ownership: 16 groups of 64 lanes; groups 0-7 sum 10 partial
    // rows, groups 8-15 sum 9 (8*10 + 8*9 = 152).
    const int c0 = r0, nc = nrows;
    const int cl = tid & 63;
    const int cg = tid >> 6;
    const int cbase = cg * 9 + min(cg, 8);
    const int ccnt  = (cg < 8) ? 10 : 9;

    __shared__ unsigned long long sredA[2][32];    // packed (S_r0,S_r1) per warp
    __shared__ unsigned long long sredB[2][32];    // packed (S_r2,S_r3) per warp
    __shared__ float csum[16][64];

    __half2 w2[4];
#pragma unroll
    for (int k = 0; k < 4; k++) w2[k] = __float2half2_rn(1.0f);  // v = 0 at iteration 1

    // direct-LDG prefetch: monotonic virtual row -> band row (wraps across iters)
    const int total = NITER * nrows;
    const uint2* gband = reinterpret_cast<const uint2*>(g_E8 + (size_t)r0 * (MDIM / 4));
    int vi = 0, vr = 0;
    uint2 raw[4], nxt[4];

    auto issue1 = [&](uint2& dst) {
        if (vi < total) dst = gband[(size_t)vr * 1024 + tid];
        vi++;
        if (++vr == nrows) vr = 0;
    };

#pragma unroll
    for (int d = 0; d < 4; d++) issue1(raw[d]);    // prologue

    unsigned gen = 0;

    for (int it = 0; it < NITER; it++) {
        __half2 cacc[4];
#pragma unroll
        for (int k = 0; k < 4; k++) cacc[k] = __float2half2_rn(0.f);

        int pp = 0;
        int r  = r0;

        // ---- row phase: groups of 4 rows, ONE __syncthreads per group ----
        for (; r + 3 < r1; r += 4, pp ^= 1) {
            __half2 l0 = row_lsum(raw[0], w2);
            __half2 l1 = row_lsum(raw[1], w2);
            __half2 l2 = row_lsum(raw[2], w2);
            __half2 l3 = row_lsum(raw[3], w2);

            issue1(nxt[0]); issue1(nxt[1]); issue1(nxt[2]); issue1(nxt[3]);  // overlap

            float2 f0 = __half22float2(l0), f1 = __half22float2(l1);
            float2 f2 = __half22float2(l2), f3 = __half22float2(l3);
            float ws0 = warp_sum(f0.x + f0.y);
            float ws1 = warp_sum(f1.x + f1.y);
            float ws2 = warp_sum(f2.x + f2.y);
            float ws3 = warp_sum(f3.x + f3.y);
            if ((tid & 31) == 0) {
                sredA[pp][tid >> 5] = pk2(ws0, ws1);
                sredB[pp][tid >> 5] = pk2(ws2, ws3);
            }
            __syncthreads();                       // the ONLY barrier this group

            unsigned long long SA = bfly_sum2(sredA[pp][tid & 31]);
            unsigned long long SB = bfly_sum2(sredB[pp][tid & 31]);
            float S0, S1, S2, S3;
            upk2(SA, S0, S1); upk2(SB, S2, S3);

            float z0 = __fdividef(ZSCALE_K, S0);   // z' = z * 2^20
            float z1 = __fdividef(ZSCALE_K, S1);
            float z2 = __fdividef(ZSCALE_K, S2);
            float z3 = __fdividef(ZSCALE_K, S3);
            if (tid == 0) {
                g_z[r] = z0; g_z[r + 1] = z1; g_z[r + 2] = z2; g_z[r + 3] = z3;
            }

            row_cacc(raw[0], __float2half2_rn(z0), cacc);
            row_cacc(raw[1], __float2half2_rn(z1), cacc);
            row_cacc(raw[2], __float2half2_rn(z2), cacc);
            row_cacc(raw[3], __float2half2_rn(z3), cacc);

            raw[0] = nxt[0]; raw[1] = nxt[1]; raw[2] = nxt[2]; raw[3] = nxt[3];
        }
        // tail rows (nrows % 4), one at a time; FIFO shift by 1
        for (; r < r1; r++, pp ^= 1) {
            uint2 a0 = raw[0];
            raw[0] = raw[1]; raw[1] = raw[2]; raw[2] = raw[3];
            issue1(raw[3]);

            __half2 l0 = row_lsum(a0, w2);
            float2 f0 = __half22float2(l0);
            float ws0 = warp_sum(f0.x + f0.y);
            if ((tid & 31) == 0) sredA[pp][tid >> 5] = pk2(ws0, 0.f);
            __syncthreads();
            unsigned long long SA = bfly_sum2(sredA[pp][tid & 31]);
            float S0, Sx; upk2(SA, S0, Sx);
            float z0 = __fdividef(ZSCALE_K, S0);
            if (tid == 0) g_z[r] = z0;
            row_cacc(a0, __float2half2_rn(z0), cacc);
        }

        // writeout column partials (thread owns cols [8t, 8t+8))
        {
            float* outp = g_part + (size_t)b * MDIM + (tid << 3);
            float2 fa = __half22float2(cacc[0]);
            float2 fb = __half22float2(cacc[1]);
            float2 fc = __half22float2(cacc[2]);
            float2 fd = __half22float2(cacc[3]);
            float4 o0; o0.x = fa.x; o0.y = fa.y; o0.z = fb.x; o0.w = fb.y;
            float4 o1; o1.x = fc.x; o1.y = fc.y; o1.z = fd.x; o1.w = fd.y;
            *reinterpret_cast<float4*>(outp)     = o0;
            *reinterpret_cast<float4*>(outp + 4) = o1;
        }

        grid_bar(++gen);    // partials visible everywhere

        // ---- column reduce: w_j = 64 / sum_b P[b][j] for my columns ----
        {
            float s = 0.f;
            if (cl < nc) {
                const float* p = g_part + (size_t)cbase * MDIM + (c0 + cl);
#pragma unroll
                for (int k = 0; k < 10; k++)
                    if (k < ccnt) s += p[(size_t)k * MDIM];
            }
            csum[cg][cl] = s;
            __syncthreads();
            if (cg == 0 && cl < nc) {
                float t = 0.f;
#pragma unroll
                for (int q = 0; q < 16; q++) t += csum[q][cl];   // fixed order
                g_w[c0 + cl] = __fdividef(ZSCALE_K, t);
            }
        }

        grid_bar(++gen);    // w visible everywhere

        if (it + 1 < NITER) {                      // reload my 8 w values (L2-hot)
            const float* wp = g_w + (tid << 3);
            float4 a = *reinterpret_cast<const float4*>(wp);
            float4 c = *reinterpret_cast<const float4*>(wp + 4);
            w2[0] = __floats2half2_rn(a.x, a.y); w2[1] = __floats2half2_rn(a.z, a.w);
            w2[2] = __floats2half2_rn(c.x, c.y); w2[3] = __floats2half2_rn(c.z, c.w);
        }
    }
}

// Final loss pass over the fp32 matrix, 1024 threads (8 cols/thread -> ~50 regs,
// occ 50%). ONE __syncthreads per row; per-warp max-shifted partials (32 warps);
// warp 0 recombines.
//  L_i = LSE_j(scale*s); base = exp(s)*w_j; rowq = z'_i/64
//  per_row = beta*(L*SumQ - scale*Sum(s*Q)) + (1-beta)*(L - scale*s_ii)
__global__ void __launch_bounds__(TPB, 1) k_final(const float* __restrict__ Sm,
                                                  const float* __restrict__ scale_p) {
    const int tid = threadIdx.x;
    const int b   = blockIdx.x;
    const int r0  = (b * MDIM) / NBLK;
    const int r1  = ((b + 1) * MDIM) / NBLK;
    const float L2E   = 1.4426950408889634f;
    const float scale = *scale_p;
    const float sL2E  = scale * L2E;

    float w[8];
    {
        const float* wp = g_w + (tid << 3);
        float4 a = *reinterpret_cast<const float4*>(wp);
        float4 c = *reinterpret_cast<const float4*>(wp + 4);
        w[0] = a.x; w[1] = a.y; w[2] = a.z; w[3] = a.w;
        w[4] = c.x; w[5] = c.y; w[6] = c.z; w[7] = c.w;
    }

    __shared__ float sM[2][32], sA[2][32], sB[2][32], sC[2][32];
    __shared__ float sdiag[2];
    float rowloss = 0.f;

    // depth-1 prefetch: 2x LDG.128 per row (cols 8t..8t+7)
    float4 nxt0, nxt1;
    {
        const float4* row = reinterpret_cast<const float4*>(Sm + (size_t)r0 * MDIM);
        nxt0 = row[(tid << 1)];
        nxt1 = row[(tid << 1) + 1];
    }

    for (int r = r0; r < r1; r++) {
        const int p = (r - r0) & 1;
        float val[8];
        val[0] = nxt0.x; val[1] = nxt0.y; val[2] = nxt0.z; val[3] = nxt0.w;
        val[4] = nxt1.x; val[5] = nxt1.y; val[6] = nxt1.z; val[7] = nxt1.w;
        if (r + 1 < r1) {
            const float4* row = reinterpret_cast<const float4*>(Sm + (size_t)(r + 1) * MDIM);
            nxt0 = row[(tid << 1)];
            nxt1 = row[(tid << 1) + 1];
        }

        float m = val[0];
#pragma unroll
        for (int k = 1; k < 8; k++) m = fmaxf(m, val[k]);
        float mw = warp_max(m);                       // per-warp max

        float negmwL = -mw * sL2E;
        float aE = 0.f, aB = 0.f, aSB = 0.f;
#pragma unroll
        for (int k = 0; k < 8; k++) {
            float s = val[k];
            aE += exp2f(fmaf(s, sL2E, negmwL));       // exp(scale*(s-mw)) <= 1
            float base = exp2f(s * L2E) * w[k];       // exp(s+v)
            aB += base;
            aSB = fmaf(s, base, aSB);
        }
        aE = warp_sum(aE); aB = warp_sum(aB); aSB = warp_sum(aSB);

        if (tid == (r >> 3)) sdiag[p] = val[r & 7];   // owner of column r
        if ((tid & 31) == 0) {
            int q = tid >> 5;
            sM[p][q] = mw; sA[p][q] = aE; sB[p][q] = aB; sC[p][q] = aSB;
        }
        __syncthreads();                              // the ONLY barrier this row

        if (tid < 32) {                               // warp 0 recombines 32 partials
            float mq = sM[p][tid];
            float M  = warp_max(mq);
            float tE = exp2f((mq - M) * sL2E) * sA[p][tid];
            float SE = warp_sum(tE);
            float SB = warp_sum(sB[p][tid]);
            float SC = warp_sum(sC[p][tid]);
            if (tid == 0) {
                float L    = fmaf(scale, M, __logf(SE));
                float rowq = g_z[r] * RQ_FIX;         // exp(u + log(m+n))
                rowloss += BETA * (L * (SB * rowq) - scale * (SC * rowq))
                         + (1.f - BETA) * (L - scale * sdiag[p]);
            }
        }
    }
    if (tid == 0) g_losspart[b] = rowloss;
}

// final scalar: mean over rows (fixed-order reduction -> deterministic)
__global__ void k_loss(float* __restrict__ out) {
    int tid = threadIdx.x;
    float v = (tid < NBLK) ? g_losspart[tid] : 0.f;
    v = warp_sum(v);
    __shared__ float sred[8];
    if ((tid & 31) == 0) sred[tid >> 5] = v;
    __syncthreads();
    if (tid == 0) {
        float t = 0.f;
#pragma unroll
        for (int q = 0; q < 8; q++) t += sred[q];
        out[0] = t / (float)MDIM;
    }
}

extern "C" void kernel_launch(void* const* d_in, const int* in_sizes, int n_in,
                              void* d_out, int out_size) {
    (void)in_sizes; (void)n_in; (void)out_size;
    const float* Sm    = (const float*)d_in[0];   // similarity_matrix [8192,8192] f32
    const float* scale = (const float*)d_in[1];   // logit_scale scalar f32
    float* out = (float*)d_out;

    k_init<<<MDIM / TPBC, TPBC>>>();
    k_convert<<<(int)(((size_t)MDIM * MDIM / 4) / TPBC), TPBC>>>(Sm);
    k_sinkhorn<<<NBLK, TPB>>>();
    k_final<<<NBLK, TPB>>>(Sm, scale);
    k_loss<<<1, TPBC>>>(out);
}

// round 17
// speedup vs baseline: 1.2218x; 1.2218x over previous
#include <cuda_runtime.h>
#include <cuda_fp16.h>
#include <cuda_fp8.h>
#include <cstdint>

// Problem constants (fixed by the reference: m = n = 8192, 50 Sinkhorn iters, beta=0.3)
#define MDIM  8192
#define NBLK  152          // GB300 SM count -> one resident wave at occ 1 (152 = 8*19)
#define TPB   512          // 16 warps; measured best (1024 regressed both kernels)
#define TPBC  256          // helper kernels
#define NITER 50
#define BETA  0.3f

// z is carried SCALED: z' = z * 2^20 (true z ~5e-9 underflows fp16).
// The scale cancels in the w update: z' = 64/S, w = 64/colsum' (2^-14 * 2^20 = 2^6).
#define ZSCALE_K 64.0f
#define RQ_FIX   0.015625f // rowq = z*16384 = z' * 16384/2^20 = z'/64

// ---- scratch (device globals: no allocation allowed in kernel_launch) ----
static __device__ uint32_t g_E8[(size_t)MDIM * MDIM / 4]; // E = exp(s) in e4m3 (64 MB)
static __device__ float  g_w[MDIM];                     // w_j = exp(v_j)
static __device__ float  g_z[MDIM];                     // z'_i = exp(u_i)*2^20 (last iter's)
static __device__ float  g_part[(size_t)NBLK * MDIM];   // per-block column partial sums
static __device__ float  g_losspart[NBLK];              // per-block loss partials
static __device__ unsigned g_cnt;                       // grid-barrier arrive counter
static __device__ unsigned g_gen;                       // grid-barrier generation

__device__ __forceinline__ float warp_sum(float v) {
#pragma unroll
    for (int o = 16; o; o >>= 1) v += __shfl_xor_sync(0xffffffffu, v, o);
    return v;
}
__device__ __forceinline__ float warp_max(float v) {
#pragma unroll
    for (int o = 16; o; o >>= 1) v = fmaxf(v, __shfl_xor_sync(0xffffffffu, v, o));
    return v;
}

// ---- packed f32x2 helpers (sm_103a FADD2 via PTX) ----
__device__ __forceinline__ unsigned long long pk2(float x, float y) {
    unsigned long long u; asm("mov.b64 %0,{%1,%2};" : "=l"(u) : "f"(x), "f"(y)); return u;
}
__device__ __forceinline__ void upk2(unsigned long long u, float& x, float& y) {
    asm("mov.b64 {%0,%1},%2;" : "=f"(x), "=f"(y) : "l"(u));
}
__device__ __forceinline__ unsigned long long add2p(unsigned long long a, unsigned long long b) {
    unsigned long long d;
    asm("add.rn.f32x2 %0,%1,%2;" : "=l"(d) : "l"(a), "l"(b));
    return d;
}
// fixed-order tree sum of 16 packed f32x2 entries
__device__ __forceinline__ unsigned long long tree16(const unsigned long long* __restrict__ A) {
    unsigned long long t0 = add2p(A[0],  A[1]);
    unsigned long long t1 = add2p(A[2],  A[3]);
    unsigned long long t2 = add2p(A[4],  A[5]);
    unsigned long long t3 = add2p(A[6],  A[7]);
    unsigned long long t4 = add2p(A[8],  A[9]);
    unsigned long long t5 = add2p(A[10], A[11]);
    unsigned long long t6 = add2p(A[12], A[13]);
    unsigned long long t7 = add2p(A[14], A[15]);
    t0 = add2p(t0, t1); t2 = add2p(t2, t3); t4 = add2p(t4, t5); t6 = add2p(t6, t7);
    t0 = add2p(t0, t2); t4 = add2p(t4, t6);
    return add2p(t0, t4);
}

// ---- e4m3x2 -> half2 (measured end-to-end rel_err 1.63e-4; e5m2 was 6.98e-4) ----
__device__ __forceinline__ __half2 cvt8(unsigned short p) {
    __half2_raw r = __nv_cvt_fp8x2_to_halfraw2((__nv_fp8x2_storage_t)p, __NV_E4M3);
    return *reinterpret_cast<__half2*>(&r);
}

// Device-wide barrier: all NBLK CTAs resident (one wave, occ 1). Deterministic.
__device__ __forceinline__ void grid_bar(unsigned want) {
    __syncthreads();
    if (threadIdx.x == 0) {
        __threadfence();
        unsigned a = atomicAdd(&g_cnt, 1u);
        if (a == NBLK - 1u) {
            atomicExch(&g_cnt, 0u);
            __threadfence();
            atomicExch(&g_gen, want);           // release
        } else {
            while (*((volatile unsigned*)&g_gen) < want) __nanosleep(64);
        }
        __threadfence();                         // acquire
    }
    __syncthreads();
}

// barrier reset + w <- 1  (runs once per graph replay)
__global__ void k_init() {
    int j = blockIdx.x * blockDim.x + threadIdx.x;
    if (j < MDIM) g_w[j] = 1.0f;
    if (j == 0) { g_cnt = 0u; g_gen = 0u; }
}

// E = exp(s) in e4m3 (one pass; iterations read 1/4 of the fp32 bytes, do NO exp)
__global__ void k_convert(const float* __restrict__ in) {
    const float L2E = 1.4426950408889634f;
    size_t i = (size_t)blockIdx.x * blockDim.x + threadIdx.x;   // float4 index
    float4 f = reinterpret_cast<const float4*>(in)[i];
    float e0 = exp2f(f.x * L2E), e1 = exp2f(f.y * L2E);
    float e2 = exp2f(f.z * L2E), e3 = exp2f(f.w * L2E);
    uint32_t lo = __nv_cvt_float2_to_fp8x2(make_float2(e0, e1), __NV_SATFINITE, __NV_E4M3);
    uint32_t hi = __nv_cvt_float2_to_fp8x2(make_float2(e2, e3), __NV_SATFINITE, __NV_E4M3);
    g_E8[i] = lo | (hi << 16);
}

// unpack one uint4 (16 e4m3) into 8 half2 and hfma2 into lsum with w (half2)
__device__ __forceinline__ void seg_unpack8(uint4 u, const __half2* __restrict__ w2,
                                            __half2* __restrict__ e2, __half2& lsum) {
    uint32_t uu[4] = {u.x, u.y, u.z, u.w};
#pragma unroll
    for (int q = 0; q < 4; q++) {
        __half2 elo = cvt8((unsigned short)(uu[q] & 0xffffu));
        __half2 ehi = cvt8((unsigned short)(uu[q] >> 16));
        e2[2 * q]     = elo;
        e2[2 * q + 1] = ehi;
        lsum = __hfma2(elo, w2[2 * q],     lsum);
        lsum = __hfma2(ehi, w2[2 * q + 1], lsum);
    }
}

// Persistent multiplicative Sinkhorn, e4m3 storage + fp16 inner math.
// (r13 structure verbatim — the measured-best config — with NBLK=152.)
//   S_i = sum_j E_ij*w_j ; z'_i = 64/S_i ; colsum'_j = sum_i E_ij*z'_i ; w_j = 64/colsum'_j
// DIRECT-LDG 4-row register prefetch; groups of 4 rows, ONE __syncthreads per
// group; wrap-around virtual row counter keeps prefetch running across
// iterations. Thread t owns cols [16t, 16t+16).
__global__ void __launch_bounds__(TPB, 1) k_sinkhorn() {
    const int tid = threadIdx.x;
    const int b   = blockIdx.x;
    const int r0  = (b * MDIM) / NBLK;
    const int r1  = ((b + 1) * MDIM) / NBLK;
    const int nrows = r1 - r0;

    // column-reduce ownership (same [c0,c1) as rows); 8 groups of 64 lanes,
    // each sums 19 of the 152 partial rows (8*19 = 152 exactly).
    const int c0 = r0, nc = nrows;
    const int cl = tid & 63;
    const int cg = tid >> 6;
    const int cbase = cg * 19;

    __shared__ unsigned long long sredA[2][16];    // packed (S_r0,S_r1) per warp
    __shared__ unsigned long long sredB[2][16];    // packed (S_r2,S_r3) per warp
    __shared__ float csum[8][64];

    __half2 w2[8];
#pragma unroll
    for (int k = 0; k < 8; k++) w2[k] = __float2half2_rn(1.0f);   // v = 0 at iteration 1

    // direct-LDG prefetch machinery: monotonic virtual row -> band row (wraps)
    const int total = NITER * nrows;
    const uint4* gband = reinterpret_cast<const uint4*>(g_E8 + (size_t)r0 * (MDIM / 4));
    int vi = 0;          // issued virtual rows
    int vr = 0;          // vi % nrows (kept by increment/wrap, no divide)
    uint4 raw[4];

    auto issue1 = [&](uint4& dst) {
        if (vi < total) dst = gband[(size_t)vr * 512 + tid];
        vi++;
        if (++vr == nrows) vr = 0;
    };

#pragma unroll
    for (int d = 0; d < 4; d++) issue1(raw[d]);    // prologue: 4 rows in flight

    unsigned gen = 0;

    for (int it = 0; it < NITER; it++) {
        __half2 cacc[8];
#pragma unroll
        for (int k = 0; k < 8; k++) cacc[k] = __float2half2_rn(0.f);

        int pp = 0;
        int r  = r0;

        // ---- row phase: groups of 4 rows, ONE __syncthreads per group ----
        for (; r + 3 < r1; r += 4, pp ^= 1) {
            uint4 a0 = raw[0], b0 = raw[1], c0v = raw[2], d0 = raw[3];
            issue1(raw[0]); issue1(raw[1]); issue1(raw[2]); issue1(raw[3]);

            __half2 eA[8], eB[8], eC[8], eD[8];
            __half2 l0 = __float2half2_rn(0.f), l1 = l0, l2 = l0, l3 = l0;
            seg_unpack8(a0,  w2, eA, l0);
            seg_unpack8(b0,  w2, eB, l1);
            seg_unpack8(c0v, w2, eC, l2);
            seg_unpack8(d0,  w2, eD, l3);

            float2 f0 = __half22float2(l0), f1 = __half22float2(l1);
            float2 f2 = __half22float2(l2), f3 = __half22float2(l3);
            float ws0 = warp_sum(f0.x + f0.y);     // 4 independent chains -> ILP
            float ws1 = warp_sum(f1.x + f1.y);
            float ws2 = warp_sum(f2.x + f2.y);
            float ws3 = warp_sum(f3.x + f3.y);
            if ((tid & 31) == 0) {
                sredA[pp][tid >> 5] = pk2(ws0, ws1);
                sredB[pp][tid >> 5] = pk2(ws2, ws3);
            }
            __syncthreads();                       // the ONLY barrier this group

            unsigned long long S01 = tree16(sredA[pp]);
            unsigned long long S23 = tree16(sredB[pp]);
            float S0, S1, S2, S3;
            upk2(S01, S0, S1); upk2(S23, S2, S3);

            float z0 = __fdividef(ZSCALE_K, S0);   // z' = z * 2^20
            float z1 = __fdividef(ZSCALE_K, S1);
            float z2 = __fdividef(ZSCALE_K, S2);
            float z3 = __fdividef(ZSCALE_K, S3);
            if (tid == 0) {
                g_z[r] = z0; g_z[r + 1] = z1; g_z[r + 2] = z2; g_z[r + 3] = z3;
            }

            __half2 z0h = __float2half2_rn(z0), z1h = __float2half2_rn(z1);
            __half2 z2h = __float2half2_rn(z2), z3h = __float2half2_rn(z3);
#pragma unroll
            for (int k = 0; k < 8; k++) {
                cacc[k] = __hfma2(eA[k], z0h, cacc[k]);
                cacc[k] = __hfma2(eB[k], z1h, cacc[k]);
                cacc[k] = __hfma2(eC[k], z2h, cacc[k]);
                cacc[k] = __hfma2(eD[k], z3h, cacc[k]);
            }
        }
        // tail rows (nrows % 4 != 0), one at a time; rotate the 4-deep buffer by 1
        for (; r < r1; r++, pp ^= 1) {
            uint4 a0 = raw[0];
            raw[0] = raw[1]; raw[1] = raw[2]; raw[2] = raw[3];
            issue1(raw[3]);

            __half2 eA[8];
            __half2 l0 = __float2half2_rn(0.f);
            seg_unpack8(a0, w2, eA, l0);
            float2 f0 = __half22float2(l0);
            float ws0 = warp_sum(f0.x + f0.y);
            if ((tid & 31) == 0) sredA[pp][tid >> 5] = pk2(ws0, 0.f);
            __syncthreads();
            unsigned long long S2p = tree16(sredA[pp]);
            float S0, Sx; upk2(S2p, S0, Sx);
            float z0 = __fdividef(ZSCALE_K, S0);
            if (tid == 0) g_z[r] = z0;
            __half2 z0h = __float2half2_rn(z0);
#pragma unroll
            for (int k = 0; k < 8; k++) cacc[k] = __hfma2(eA[k], z0h, cacc[k]);
        }

        // writeout column partials (convert fp16 accumulators to fp32 once)
        {
            float* outp = g_part + (size_t)b * MDIM + (tid << 4);
#pragma unroll
            for (int g = 0; g < 4; g++) {
                float2 fa = __half22float2(cacc[2 * g]);
                float2 fb = __half22float2(cacc[2 * g + 1]);
                float4 o; o.x = fa.x; o.y = fa.y; o.z = fb.x; o.w = fb.y;
                *reinterpret_cast<float4*>(outp + 4 * g) = o;
            }
        }

        grid_bar(++gen);    // partials visible everywhere

        // ---- column reduce: w_j = 64 / sum_b P[b][j] for my columns ----
        {
            float s = 0.f;
            if (cl < nc) {
                const float* p = g_part + (size_t)cbase * MDIM + (c0 + cl);
#pragma unroll
                for (int k = 0; k < 19; k++) s += p[(size_t)k * MDIM];
            }
            csum[cg][cl] = s;
            __syncthreads();
            if (cg == 0 && cl < nc) {
                float t = 0.f;
#pragma unroll
                for (int q = 0; q < 8; q++) t += csum[q][cl];    // fixed order
                g_w[c0 + cl] = __fdividef(ZSCALE_K, t);
            }
        }

        grid_bar(++gen);    // w visible everywhere

        if (it + 1 < NITER) {                      // reload my 16 w values (L2-hot)
            const float* wp = g_w + (tid << 4);
            float4 a = *reinterpret_cast<const float4*>(wp);
            float4 c = *reinterpret_cast<const float4*>(wp + 4);
            float4 d = *reinterpret_cast<const float4*>(wp + 8);
            float4 e = *reinterpret_cast<const float4*>(wp + 12);
            w2[0] = __floats2half2_rn(a.x, a.y); w2[1] = __floats2half2_rn(a.z, a.w);
            w2[2] = __floats2half2_rn(c.x, c.y); w2[3] = __floats2half2_rn(c.z, c.w);
            w2[4] = __floats2half2_rn(d.x, d.y); w2[5] = __floats2half2_rn(d.z, d.w);
            w2[6] = __floats2half2_rn(e.x, e.y); w2[7] = __floats2half2_rn(e.z, e.w);
        }
    }
}

// Final loss pass over the fp32 matrix (r13 form verbatim — measured 89.4us at
// NBLK=152 in round 15). ONE __syncthreads per row; per-warp max-shifted
// partials; warp 0 recombines.
//  L_i = LSE_j(scale*s); base = exp(s)*w_j; rowq = z'_i/64
//  per_row = beta*(L*SumQ - scale*Sum(s*Q)) + (1-beta)*(L - scale*s_ii)
__global__ void __launch_bounds__(TPB, 1) k_final(const float* __restrict__ Sm,
                                                  const float* __restrict__ scale_p) {
    const int tid = threadIdx.x;
    const int b   = blockIdx.x;
    const int r0  = (b * MDIM) / NBLK;
    const int r1  = ((b + 1) * MDIM) / NBLK;
    const float L2E   = 1.4426950408889634f;
    const float scale = *scale_p;
    const float sL2E  = scale * L2E;

    float w[16];
#pragma unroll
    for (int g = 0; g < 2; g++) {
        int cb = (g << 12) + (tid << 3);
        float4 a = *reinterpret_cast<const float4*>(g_w + cb);
        float4 c = *reinterpret_cast<const float4*>(g_w + cb + 4);
        w[g * 8 + 0] = a.x; w[g * 8 + 1] = a.y; w[g * 8 + 2] = a.z; w[g * 8 + 3] = a.w;
        w[g * 8 + 4] = c.x; w[g * 8 + 5] = c.y; w[g * 8 + 6] = c.z; w[g * 8 + 7] = c.w;
    }

    __shared__ float sM[2][16], sA[2][16], sB[2][16], sC[2][16];
    __shared__ float sdiag[2];
    float rowloss = 0.f;

    float4 nxt[4];
    {
        const float4* row = reinterpret_cast<const float4*>(Sm + (size_t)r0 * MDIM);
#pragma unroll
        for (int g = 0; g < 2; g++) {
            nxt[2 * g]     = row[(g << 10) + (tid << 1)];
            nxt[2 * g + 1] = row[(g << 10) + (tid << 1) + 1];
        }
    }

    for (int r = r0; r < r1; r++) {
        const int p = (r - r0) & 1;
        float val[16];
#pragma unroll
        for (int g = 0; g < 2; g++) {
            float4 a = nxt[2 * g], c = nxt[2 * g + 1];
            val[g * 8 + 0] = a.x; val[g * 8 + 1] = a.y; val[g * 8 + 2] = a.z; val[g * 8 + 3] = a.w;
            val[g * 8 + 4] = c.x; val[g * 8 + 5] = c.y; val[g * 8 + 6] = c.z; val[g * 8 + 7] = c.w;
        }
        if (r + 1 < r1) {
            const float4* row = reinterpret_cast<const float4*>(Sm + (size_t)(r + 1) * MDIM);
#pragma unroll
            for (int g = 0; g < 2; g++) {
                nxt[2 * g]     = row[(g << 10) + (tid << 1)];
                nxt[2 * g + 1] = row[(g << 10) + (tid << 1) + 1];
            }
        }

        float m = val[0];
#pragma unroll
        for (int k = 1; k < 16; k++) m = fmaxf(m, val[k]);
        float mw = warp_max(m);                       // per-warp max

        float negmwL = -mw * sL2E;
        float aE = 0.f, aB = 0.f, aSB = 0.f;
#pragma unroll
        for (int k = 0; k < 16; k++) {
            float s = val[k];
            aE += exp2f(fmaf(s, sL2E, negmwL));       // exp(scale*(s-mw)) <= 1
            float base = exp2f(s * L2E) * w[k];       // exp(s+v)
            aB += base;
            aSB = fmaf(s, base, aSB);
        }
        aE = warp_sum(aE); aB = warp_sum(aB); aSB = warp_sum(aSB);

        if (tid == ((r & 4095) >> 3)) sdiag[p] = val[((r >> 12) << 3) + (r & 7)]; // col r owner
        if ((tid & 31) == 0) {
            int q = tid >> 5;
            sM[p][q] = mw; sA[p][q] = aE; sB[p][q] = aB; sC[p][q] = aSB;
        }
        __syncthreads();                              // the ONLY barrier this row

        if (tid < 32) {                               // warp 0 recombines
            int q = tid & 15;
            float mq = sM[p][q];
            float M  = warp_max((tid < 16) ? mq : -3.4e38f);
            float tE = (tid < 16) ? exp2f((mq - M) * sL2E) * sA[p][q] : 0.f;
            float tB = (tid < 16) ? sB[p][q] : 0.f;
            float tC = (tid < 16) ? sC[p][q] : 0.f;
            float SE = warp_sum(tE);
            float SB = warp_sum(tB);
            float SC = warp_sum(tC);
            if (tid == 0) {
                float L    = fmaf(scale, M, __logf(SE));
                float rowq = g_z[r] * RQ_FIX;         // exp(u + log(m+n))
                rowloss += BETA * (L * (SB * rowq) - scale * (SC * rowq))
                         + (1.f - BETA) * (L - scale * sdiag[p]);
            }
        }
    }
    if (tid == 0) g_losspart[b] = rowloss;
}

// final scalar: mean over rows (fixed-order reduction -> deterministic)
__global__ void k_loss(float* __restrict__ out) {
    int tid = threadIdx.x;
    float v = (tid < NBLK) ? g_losspart[tid] : 0.f;
    v = warp_sum(v);
    __shared__ float sred[8];
    if ((tid & 31) == 0) sred[tid >> 5] = v;
    __syncthreads();
    if (tid == 0) {
        float t = 0.f;
#pragma unroll
        for (int q = 0; q < 8; q++) t += sred[q];
        out[0] = t / (float)MDIM;
    }
}

extern "C" void kernel_launch(void* const* d_in, const int* in_sizes, int n_in,
                              void* d_out, int out_size) {
    (void)in_sizes; (void)n_in; (void)out_size;
    const float* Sm    = (const float*)d_in[0];   // similarity_matrix [8192,8192] f32
    const float* scale = (const float*)d_in[1];   // logit_scale scalar f32
    float* out = (float*)d_out;

    k_init<<<MDIM / TPBC, TPBC>>>();
    k_convert<<<(int)(((size_t)MDIM * MDIM / 4) / TPBC), TPBC>>>(Sm);
    k_sinkhorn<<<NBLK, TPB>>>();
    k_final<<<NBLK, TPB>>>(Sm, scale);
    k_loss<<<1, TPBC>>>(out);
}